// round 5
// baseline (speedup 1.0000x reference)
#include <cuda_runtime.h>

// Problem constants
#define B_ROWS   65536
#define N_SPARSE 26
#define VOCAB    5000
#define N_DENSE  13

#define NBLOCKS     148
#define THREADS     1024
#define ROWS_PB     443           // ceil(65536/148); last block has 415
#define IDX_STRIDE  27            // pad 26 -> 27 for conflict-light smem reads

// Feature split: features [0,17) via smem table slices (3 passes of 6/6/5),
// features [17,26) + 2 cross tables direct through L1/L2/DRAM.
#define N_CACHED    17
#define PASS_MAX    6

// Dynamic smem layout (bytes)
#define TABLE_BYTES (PASS_MAX * VOCAB * 4)        // 120000
#define IDX_BYTES   (ROWS_PB * IDX_STRIDE * 4)    // 47844
#define DENSE_BYTES (ROWS_PB * N_DENSE * 4)       // 23036
#define SMEM_TOTAL  (TABLE_BYTES + IDX_BYTES + DENSE_BYTES)   // 190880

// Two threads per row: sub 0 / sub 1 split the per-row work; pair-combined
// via shfl_xor(1). All 1024 threads help with staging and table copies.

__global__ __launch_bounds__(THREADS, 1) void wide_kernel(
    const float* __restrict__ dense,        // [B, 13]
    const float* __restrict__ emb_table,    // [26, 5000]
    const float* __restrict__ cross_table0, // [25e6]
    const float* __restrict__ cross_table1, // [25e6]
    const float* __restrict__ dense_w,      // [13]
    const int*   __restrict__ sparse_idx,   // [B, 26] int32
    float*       __restrict__ out)          // [B]
{
    extern __shared__ char smem[];
    float* s_table = (float*)smem;
    int*   s_idx   = (int*)(smem + TABLE_BYTES);
    float* s_dense = (float*)(smem + TABLE_BYTES + IDX_BYTES);

    const int tid  = threadIdx.x;
    const int row0 = blockIdx.x * ROWS_PB;
    const int rows = min(ROWS_PB, B_ROWS - row0);

    // ---- Stage sparse_idx (coalesced -> stride-27 smem) ----
    const int nidx = rows * N_SPARSE;
    for (int j = tid; j < nidx; j += THREADS) {
        int v = __ldg(&sparse_idx[row0 * N_SPARSE + j]);
        int r = j / N_SPARSE;
        int c = j - r * N_SPARSE;
        s_idx[r * IDX_STRIDE + c] = v;
    }
    // ---- Stage dense (coalesced, natural stride-13) ----
    const int nden = rows * N_DENSE;
    for (int j = tid; j < nden; j += THREADS) {
        s_dense[j] = __ldg(&dense[row0 * N_DENSE + j]);
    }
    __syncthreads();

    const int  sub     = tid & 1;            // which half of the row's work
    const int  rawrow  = tid >> 1;
    const bool active  = (rawrow < rows);
    const int  myrow   = active ? rawrow : (rows - 1);   // clamp: safe reads only
    const int* my      = &s_idx[myrow * IDX_STRIDE];

    float acc = 0.0f;

    // ---- Direct gathers (split across the pair), issued before first copy ----
    if (sub == 0) {
        // features 17..21 + cross0
        #pragma unroll
        for (int f = 17; f < 22; f++)
            acc += __ldg(&emb_table[f * VOCAB + my[f]]);
        acc += __ldg(&cross_table0[my[0] * VOCAB + my[1]]);
    } else {
        // features 22..25 + cross1
        #pragma unroll
        for (int f = 22; f < 26; f++)
            acc += __ldg(&emb_table[f * VOCAB + my[f]]);
        acc += __ldg(&cross_table1[my[2] * VOCAB + my[3]]);
    }

    // ---- Dense dot (split: sub0 -> d 0..6, sub1 -> d 7..12) ----
    {
        const float* dr = &s_dense[myrow * N_DENSE];
        const int d0 = sub ? 7 : 0;
        const int d1 = sub ? 13 : 7;
        #pragma unroll
        for (int d = 0; d < 7; d++) {
            int dd = d0 + d;
            if (dd < d1) acc += dr[dd] * __ldg(&dense_w[dd]);
        }
    }

    // ---- Cached feature passes: {6, 6, 5} over features [0, 17) ----
    #pragma unroll
    for (int p = 0; p < 3; p++) {
        const int f0 = p * PASS_MAX;
        const int nf = (p == 2) ? (N_CACHED - 2 * PASS_MAX) : PASS_MAX;   // 6,6,5

        // Cooperative copy of contiguous region [f0*VOCAB, (f0+nf)*VOCAB)
        const float4* src = (const float4*)(emb_table + f0 * VOCAB);
        float4*       dst = (float4*)s_table;
        const int nvec = nf * VOCAB / 4;
        for (int j = tid; j < nvec; j += THREADS) {
            dst[j] = __ldg(&src[j]);
        }
        __syncthreads();

        // Pair-split gathers: sub0 takes f0..f0+2, sub1 takes f0+3..f0+5
        const int gbase = sub * 3;
        #pragma unroll
        for (int f = 0; f < 3; f++) {
            int ff = gbase + f;
            if (ff < nf) acc += s_table[ff * VOCAB + my[f0 + ff]];
        }
        __syncthreads();
    }

    // ---- Pair combine + store ----
    acc += __shfl_xor_sync(0xFFFFFFFFu, acc, 1);
    if (active && sub == 0) out[row0 + rawrow] = acc;
}

extern "C" void kernel_launch(void* const* d_in, const int* in_sizes, int n_in,
                              void* d_out, int out_size)
{
    const float* dense        = nullptr;
    const float* emb_table    = nullptr;
    const float* cross_table0 = nullptr;
    const float* cross_table1 = nullptr;
    const float* dense_w      = nullptr;
    const int*   sparse_idx   = nullptr;

    for (int i = 0; i < n_in; i++) {
        const long long sz = in_sizes[i];
        if      (sz == (long long)B_ROWS * N_DENSE)   dense      = (const float*)d_in[i];
        else if (sz == (long long)N_SPARSE * VOCAB)   emb_table  = (const float*)d_in[i];
        else if (sz == (long long)VOCAB * VOCAB) {
            if (!cross_table0) cross_table0 = (const float*)d_in[i];
            else               cross_table1 = (const float*)d_in[i];
        }
        else if (sz == N_DENSE)                       dense_w    = (const float*)d_in[i];
        else if (sz == (long long)B_ROWS * N_SPARSE)  sparse_idx = (const int*)d_in[i];
    }

    float* out = (float*)d_out;

    static bool attr_set = false;
    if (!attr_set) {
        cudaFuncSetAttribute(wide_kernel,
                             cudaFuncAttributeMaxDynamicSharedMemorySize, SMEM_TOTAL);
        attr_set = true;
    }

    wide_kernel<<<NBLOCKS, THREADS, SMEM_TOTAL>>>(dense, emb_table,
                                                  cross_table0, cross_table1,
                                                  dense_w, sparse_idx, out);
}

// round 6
// speedup vs baseline: 1.3732x; 1.3732x over previous
#include <cuda_runtime.h>
#include <cstdint>

// Problem constants
#define B_ROWS   65536
#define N_SPARSE 26
#define VOCAB    5000
#define N_DENSE  13

#define NBLOCKS  148
#define THREADS  1024
#define ROWS_PB  444          // even -> all bulk-copy src offsets/sizes 16B-aligned
#define N_CACHED 18           // features [0,18) via smem; [18,26) + crosses direct
#define PASS_NF  3
#define N_PASSES 6

// Dynamic smem layout (bytes), all 16B-aligned
#define BUF_BYTES   (PASS_NF * VOCAB * 4)       // 60000
#define IDX_OFF     (2 * BUF_BYTES)             // 120000
#define IDX_BYTES   (ROWS_PB * N_SPARSE * 4)    // 46176
#define DENSE_OFF   (IDX_OFF + IDX_BYTES)       // 166176
#define DENSE_BYTES (ROWS_PB * N_DENSE * 4)     // 23088
#define MBAR_OFF    (DENSE_OFF + DENSE_BYTES)   // 189264 (8B aligned)
#define SMEM_TOTAL  (MBAR_OFF + 3 * 8)          // 189288

__device__ __forceinline__ uint32_t smem_u32(const void* p) {
    return (uint32_t)__cvta_generic_to_shared(p);
}
__device__ __forceinline__ void mbar_init(uint32_t mbar, uint32_t count) {
    asm volatile("mbarrier.init.shared.b64 [%0], %1;" :: "r"(mbar), "r"(count) : "memory");
}
__device__ __forceinline__ void mbar_expect_tx(uint32_t mbar, uint32_t bytes) {
    asm volatile("mbarrier.arrive.expect_tx.shared.b64 _, [%0], %1;"
                 :: "r"(mbar), "r"(bytes) : "memory");
}
__device__ __forceinline__ void mbar_wait(uint32_t mbar, uint32_t parity) {
    uint32_t done = 0;
    while (!done) {
        asm volatile(
            "{\n\t.reg .pred p;\n\t"
            "mbarrier.try_wait.parity.acquire.cta.shared::cta.b64 p, [%1], %2, 0x989680;\n\t"
            "selp.b32 %0, 1, 0, p;\n\t}"
            : "=r"(done) : "r"(mbar), "r"(parity) : "memory");
    }
}
__device__ __forceinline__ void bulk_g2s(uint32_t dst, const void* src,
                                         uint32_t bytes, uint32_t mbar) {
    asm volatile(
        "cp.async.bulk.shared::cta.global.mbarrier::complete_tx::bytes [%0], [%1], %2, [%3];"
        :: "r"(dst), "l"(src), "r"(bytes), "r"(mbar) : "memory");
}

__global__ __launch_bounds__(THREADS, 1) void wide_kernel(
    const float* __restrict__ dense,        // [B, 13]
    const float* __restrict__ emb_table,    // [26, 5000]
    const float* __restrict__ cross_table0, // [25e6]
    const float* __restrict__ cross_table1, // [25e6]
    const float* __restrict__ dense_w,      // [13]
    const int*   __restrict__ sparse_idx,   // [B, 26] int32
    float*       __restrict__ out)          // [B]
{
    extern __shared__ __align__(16) char smem[];
    float* s_buf[2] = { (float*)smem, (float*)(smem + BUF_BYTES) };
    int*   s_idx    = (int*)(smem + IDX_OFF);
    float* s_dense  = (float*)(smem + DENSE_OFF);

    const uint32_t mb_io = smem_u32(smem + MBAR_OFF);        // idx+dense barrier
    const uint32_t mb_b0 = smem_u32(smem + MBAR_OFF + 8);    // buffer 0 barrier
    const uint32_t mb_b1 = smem_u32(smem + MBAR_OFF + 16);   // buffer 1 barrier
    const uint32_t buf_s[2] = { smem_u32(smem), smem_u32(smem + BUF_BYTES) };
    const uint32_t mb_b[2]  = { mb_b0, mb_b1 };

    const int tid  = threadIdx.x;
    const int row0 = blockIdx.x * ROWS_PB;
    const int rows = min(ROWS_PB, B_ROWS - row0);

    if (tid == 0) {
        mbar_init(mb_io, 1);
        mbar_init(mb_b0, 1);
        mbar_init(mb_b1, 1);
    }
    __syncthreads();

    // Kick off all initial async copies from one thread.
    if (tid == 0) {
        const uint32_t idx_bytes   = (uint32_t)rows * N_SPARSE * 4;
        const uint32_t dense_bytes = (uint32_t)rows * N_DENSE * 4;
        mbar_expect_tx(mb_io, idx_bytes + dense_bytes);
        bulk_g2s(smem_u32(s_idx),   sparse_idx + (size_t)row0 * N_SPARSE, idx_bytes,   mb_io);
        bulk_g2s(smem_u32(s_dense), dense      + (size_t)row0 * N_DENSE,  dense_bytes, mb_io);

        mbar_expect_tx(mb_b0, BUF_BYTES);
        bulk_g2s(buf_s[0], emb_table + 0 * PASS_NF * VOCAB, BUF_BYTES, mb_b0);
        mbar_expect_tx(mb_b1, BUF_BYTES);
        bulk_g2s(buf_s[1], emb_table + 1 * PASS_NF * VOCAB, BUF_BYTES, mb_b1);
    }

    const int  sub    = tid & 1;
    const int  rawrow = tid >> 1;
    const bool active = (rawrow < rows);
    const int  myrow  = active ? rawrow : (rows - 1);   // clamp: safe reads only

    // Wait for idx + dense, then issue the long-latency direct gathers so they
    // overlap the still-inflight table-slice copies.
    mbar_wait(mb_io, 0);
    const int* my = &s_idx[myrow * N_SPARSE];

    float acc = 0.0f;
    if (sub == 0) {
        #pragma unroll
        for (int f = N_CACHED; f < 22; f++)          // 18..21
            acc += __ldg(&emb_table[f * VOCAB + my[f]]);
        acc += __ldg(&cross_table0[my[0] * VOCAB + my[1]]);
    } else {
        #pragma unroll
        for (int f = 22; f < N_SPARSE; f++)          // 22..25
            acc += __ldg(&emb_table[f * VOCAB + my[f]]);
        acc += __ldg(&cross_table1[my[2] * VOCAB + my[3]]);
    }

    // Dense dot, pair-split (7 / 6)
    {
        const float* dr = &s_dense[myrow * N_DENSE];
        if (sub == 0) {
            #pragma unroll
            for (int d = 0; d < 7; d++) acc += dr[d] * __ldg(&dense_w[d]);
        } else {
            #pragma unroll
            for (int d = 7; d < N_DENSE; d++) acc += dr[d] * __ldg(&dense_w[d]);
        }
    }

    // Double-buffered cached passes: 6 passes x 3 features over [0, 18).
    #pragma unroll
    for (int p = 0; p < N_PASSES; p++) {
        const int b = p & 1;
        mbar_wait(mb_b[b], (p >> 1) & 1);

        const float* tb = s_buf[b];
        const int f0 = p * PASS_NF;
        // Balance across the pair: sub==(p&1) takes 2 features, other takes 1.
        if (sub == (p & 1)) {
            acc += tb[0 * VOCAB + my[f0 + 0]];
            acc += tb[1 * VOCAB + my[f0 + 1]];
        } else {
            acc += tb[2 * VOCAB + my[f0 + 2]];
        }

        __syncthreads();   // all consumers done with buffer b

        if (p + 2 < N_PASSES && tid == 0) {
            mbar_expect_tx(mb_b[b], BUF_BYTES);
            bulk_g2s(buf_s[b], emb_table + (p + 2) * PASS_NF * VOCAB, BUF_BYTES, mb_b[b]);
        }
    }

    // Pair combine + store
    acc += __shfl_xor_sync(0xFFFFFFFFu, acc, 1);
    if (active && sub == 0) out[row0 + rawrow] = acc;
}

extern "C" void kernel_launch(void* const* d_in, const int* in_sizes, int n_in,
                              void* d_out, int out_size)
{
    const float* dense        = nullptr;
    const float* emb_table    = nullptr;
    const float* cross_table0 = nullptr;
    const float* cross_table1 = nullptr;
    const float* dense_w      = nullptr;
    const int*   sparse_idx   = nullptr;

    for (int i = 0; i < n_in; i++) {
        const long long sz = in_sizes[i];
        if      (sz == (long long)B_ROWS * N_DENSE)   dense      = (const float*)d_in[i];
        else if (sz == (long long)N_SPARSE * VOCAB)   emb_table  = (const float*)d_in[i];
        else if (sz == (long long)VOCAB * VOCAB) {
            if (!cross_table0) cross_table0 = (const float*)d_in[i];
            else               cross_table1 = (const float*)d_in[i];
        }
        else if (sz == N_DENSE)                       dense_w    = (const float*)d_in[i];
        else if (sz == (long long)B_ROWS * N_SPARSE)  sparse_idx = (const int*)d_in[i];
    }

    float* out = (float*)d_out;

    static bool attr_set = false;
    if (!attr_set) {
        cudaFuncSetAttribute(wide_kernel,
                             cudaFuncAttributeMaxDynamicSharedMemorySize, SMEM_TOTAL);
        attr_set = true;
    }

    wide_kernel<<<NBLOCKS, THREADS, SMEM_TOTAL>>>(dense, emb_table,
                                                  cross_table0, cross_table1,
                                                  dense_w, sparse_idx, out);
}

// round 7
// speedup vs baseline: 1.4102x; 1.0269x over previous
#include <cuda_runtime.h>
#include <cstdint>

// Problem constants
#define B_ROWS   65536
#define N_SPARSE 26
#define VOCAB    5000
#define N_DENSE  13

#define NBLOCKS    147
#define THREADS    1024
#define ROWS_PB    448        // 146*448=65408, last block 128 rows
#define CHUNK_ROWS 112
#define N_CHUNKS   4

#define N_CACHED 18           // features [0,18) via smem; [18,26) + crosses direct
#define PASS_NF  3
#define N_PASSES 6

// Dynamic smem layout (bytes), all 16B-aligned
#define BUF_BYTES   (PASS_NF * VOCAB * 4)       // 60000
#define IDX_OFF     (2 * BUF_BYTES)             // 120000
#define IDX_BYTES   (ROWS_PB * N_SPARSE * 4)    // 46592
#define DENSE_OFF   (IDX_OFF + IDX_BYTES)       // 166592
#define DENSE_BYTES (ROWS_PB * N_DENSE * 4)     // 23296
#define MBAR_OFF    (DENSE_OFF + DENSE_BYTES)   // 189888 (8B aligned)
// mbarriers: 4 io chunks + 2 slice buffers
#define SMEM_TOTAL  (MBAR_OFF + 6 * 8)          // 189936

__device__ __forceinline__ uint32_t smem_u32(const void* p) {
    return (uint32_t)__cvta_generic_to_shared(p);
}
__device__ __forceinline__ void mbar_init(uint32_t mbar, uint32_t count) {
    asm volatile("mbarrier.init.shared.b64 [%0], %1;" :: "r"(mbar), "r"(count) : "memory");
}
__device__ __forceinline__ void mbar_expect_tx(uint32_t mbar, uint32_t bytes) {
    asm volatile("mbarrier.arrive.expect_tx.shared.b64 _, [%0], %1;"
                 :: "r"(mbar), "r"(bytes) : "memory");
}
__device__ __forceinline__ void mbar_wait(uint32_t mbar, uint32_t parity) {
    uint32_t done = 0;
    while (!done) {
        asm volatile(
            "{\n\t.reg .pred p;\n\t"
            "mbarrier.try_wait.parity.acquire.cta.shared::cta.b64 p, [%1], %2, 0x989680;\n\t"
            "selp.b32 %0, 1, 0, p;\n\t}"
            : "=r"(done) : "r"(mbar), "r"(parity) : "memory");
    }
}
__device__ __forceinline__ void bulk_g2s(uint32_t dst, const void* src,
                                         uint32_t bytes, uint32_t mbar) {
    asm volatile(
        "cp.async.bulk.shared::cta.global.mbarrier::complete_tx::bytes [%0], [%1], %2, [%3];"
        :: "r"(dst), "l"(src), "r"(bytes), "r"(mbar) : "memory");
}

__global__ __launch_bounds__(THREADS, 1) void wide_kernel(
    const float* __restrict__ dense,        // [B, 13]
    const float* __restrict__ emb_table,    // [26, 5000]
    const float* __restrict__ cross_table0, // [25e6]
    const float* __restrict__ cross_table1, // [25e6]
    const float* __restrict__ dense_w,      // [13]
    const int*   __restrict__ sparse_idx,   // [B, 26] int32
    float*       __restrict__ out)          // [B]
{
    extern __shared__ __align__(16) char smem[];
    float* s_buf[2] = { (float*)smem, (float*)(smem + BUF_BYTES) };
    int*   s_idx    = (int*)(smem + IDX_OFF);
    float* s_dense  = (float*)(smem + DENSE_OFF);

    const uint32_t mb_io0 = smem_u32(smem + MBAR_OFF);           // 4 io chunk barriers
    const uint32_t mb_b0  = smem_u32(smem + MBAR_OFF + 32);      // slice buffer barriers
    const uint32_t buf_s[2] = { smem_u32(smem), smem_u32(smem + BUF_BYTES) };

    const int tid  = threadIdx.x;
    const int row0 = blockIdx.x * ROWS_PB;
    const int rows = min(ROWS_PB, B_ROWS - row0);

    if (tid == 0) {
        #pragma unroll
        for (int c = 0; c < N_CHUNKS; c++) mbar_init(mb_io0 + 8 * c, 1);
        mbar_init(mb_b0, 1);
        mbar_init(mb_b0 + 8, 1);
    }
    __syncthreads();

    // Issue all initial async copies: 4 io chunks (idx+dense) + 2 table slices.
    if (tid == 0) {
        #pragma unroll
        for (int c = 0; c < N_CHUNKS; c++) {
            const int crow0 = c * CHUNK_ROWS;
            const int crows = max(0, min(CHUNK_ROWS, rows - crow0));
            const uint32_t ib = (uint32_t)crows * N_SPARSE * 4;
            const uint32_t db = (uint32_t)crows * N_DENSE * 4;
            mbar_expect_tx(mb_io0 + 8 * c, ib + db);   // 0 bytes -> flips immediately
            if (crows > 0) {
                bulk_g2s(smem_u32(s_idx + crow0 * N_SPARSE),
                         sparse_idx + (size_t)(row0 + crow0) * N_SPARSE, ib, mb_io0 + 8 * c);
                bulk_g2s(smem_u32(s_dense + crow0 * N_DENSE),
                         dense + (size_t)(row0 + crow0) * N_DENSE, db, mb_io0 + 8 * c);
            }
        }
        mbar_expect_tx(mb_b0, BUF_BYTES);
        bulk_g2s(buf_s[0], emb_table + 0 * PASS_NF * VOCAB, BUF_BYTES, mb_b0);
        mbar_expect_tx(mb_b0 + 8, BUF_BYTES);
        bulk_g2s(buf_s[1], emb_table + 1 * PASS_NF * VOCAB, BUF_BYTES, mb_b0 + 8);
    }

    const int  sub    = tid & 1;
    const int  rawrow = tid >> 1;
    const bool active = (rawrow < rows);

    // Wait only for this thread's own io chunk, then launch direct gathers
    // so they overlap later io chunks and the table-slice copies.
    const int chunk = min(rawrow / CHUNK_ROWS, N_CHUNKS - 1);
    mbar_wait(mb_io0 + 8 * chunk, 0);

    const int* my = &s_idx[rawrow * N_SPARSE];
    float acc = 0.0f;

    if (active) {
        if (sub == 0) {
            acc += __ldg(&cross_table0[my[0] * VOCAB + my[1]]);     // DRAM, longest latency first
            #pragma unroll
            for (int f = N_CACHED; f < 22; f++)                     // 18..21
                acc += __ldg(&emb_table[f * VOCAB + my[f]]);
        } else {
            acc += __ldg(&cross_table1[my[2] * VOCAB + my[3]]);
            #pragma unroll
            for (int f = 22; f < N_SPARSE; f++)                     // 22..25
                acc += __ldg(&emb_table[f * VOCAB + my[f]]);
        }

        // Dense dot, pair-split (7 / 6)
        const float* dr = &s_dense[rawrow * N_DENSE];
        if (sub == 0) {
            #pragma unroll
            for (int d = 0; d < 7; d++) acc += dr[d] * __ldg(&dense_w[d]);
        } else {
            #pragma unroll
            for (int d = 7; d < N_DENSE; d++) acc += dr[d] * __ldg(&dense_w[d]);
        }
    }

    // Double-buffered cached passes: 6 passes x 3 features over [0, 18).
    #pragma unroll
    for (int p = 0; p < N_PASSES; p++) {
        const int b = p & 1;
        mbar_wait(mb_b0 + 8 * b, (p >> 1) & 1);

        if (active) {
            const float* tb = s_buf[b];
            const int f0 = p * PASS_NF;
            // Balance across the pair: one sub takes 2 features, other takes 1.
            if (sub == (p & 1)) {
                acc += tb[0 * VOCAB + my[f0 + 0]];
                acc += tb[1 * VOCAB + my[f0 + 1]];
            } else {
                acc += tb[2 * VOCAB + my[f0 + 2]];
            }
        }

        __syncthreads();   // all consumers done with buffer b

        if (p + 2 < N_PASSES && tid == 0) {
            mbar_expect_tx(mb_b0 + 8 * b, BUF_BYTES);
            bulk_g2s(buf_s[b], emb_table + (p + 2) * PASS_NF * VOCAB, BUF_BYTES, mb_b0 + 8 * b);
        }
    }

    // Pair combine + store
    acc += __shfl_xor_sync(0xFFFFFFFFu, acc, 1);
    if (active && sub == 0) out[row0 + rawrow] = acc;
}

extern "C" void kernel_launch(void* const* d_in, const int* in_sizes, int n_in,
                              void* d_out, int out_size)
{
    const float* dense        = nullptr;
    const float* emb_table    = nullptr;
    const float* cross_table0 = nullptr;
    const float* cross_table1 = nullptr;
    const float* dense_w      = nullptr;
    const int*   sparse_idx   = nullptr;

    for (int i = 0; i < n_in; i++) {
        const long long sz = in_sizes[i];
        if      (sz == (long long)B_ROWS * N_DENSE)   dense      = (const float*)d_in[i];
        else if (sz == (long long)N_SPARSE * VOCAB)   emb_table  = (const float*)d_in[i];
        else if (sz == (long long)VOCAB * VOCAB) {
            if (!cross_table0) cross_table0 = (const float*)d_in[i];
            else               cross_table1 = (const float*)d_in[i];
        }
        else if (sz == N_DENSE)                       dense_w    = (const float*)d_in[i];
        else if (sz == (long long)B_ROWS * N_SPARSE)  sparse_idx = (const int*)d_in[i];
    }

    float* out = (float*)d_out;

    static bool attr_set = false;
    if (!attr_set) {
        cudaFuncSetAttribute(wide_kernel,
                             cudaFuncAttributeMaxDynamicSharedMemorySize, SMEM_TOTAL);
        attr_set = true;
    }

    wide_kernel<<<NBLOCKS, THREADS, SMEM_TOTAL>>>(dense, emb_table,
                                                  cross_table0, cross_table1,
                                                  dense_w, sparse_idx, out);
}